// round 3
// baseline (speedup 1.0000x reference)
#include <cuda_runtime.h>

// KNNInterpolate: out[m, :] = sum_k w[m,k] * s_feats[idx[m,k], :]
//
// Inputs (metadata order):
//   d_in[0] s_feats          float32 [65536, 128]
//   d_in[1] q_points         float32 [262144, 3]
//   d_in[2] s_points         float32 [65536, 3]
//   d_in[3] neighbor_indices int32   [262144, 3]
// Output: float32 [262144, 128]

#define C_FEAT 128
#define N_SRC 65536
#define EPS 1e-8f

// Padded xyz table so a neighbor point is a single LDG.128 broadcast.
__device__ float4 g_sp_pad[N_SRC];

__global__ __launch_bounds__(256) void pack_points_kernel(
    const float* __restrict__ s_points)
{
    int i = blockIdx.x * blockDim.x + threadIdx.x;
    if (i < N_SRC) {
        float x = __ldg(s_points + 3 * i + 0);
        float y = __ldg(s_points + 3 * i + 1);
        float z = __ldg(s_points + 3 * i + 2);
        g_sp_pad[i] = make_float4(x, y, z, 0.0f);
    }
}

__device__ __forceinline__ float wgt(float4 p, float qx, float qy, float qz)
{
    float dx = qx - p.x, dy = qy - p.y, dz = qz - p.z;
    return 1.0f / (dx * dx + dy * dy + dz * dz + EPS);
}

// One warp handles TWO adjacent queries: metadata loads are vectorized,
// six independent feature-row gathers are in flight per warp iteration.
__global__ __launch_bounds__(256) void knn_interp_kernel(
    const float* __restrict__ s_feats,
    const float* __restrict__ q_points,
    const int* __restrict__ nidx,
    float4* __restrict__ out,
    int n_pairs)
{
    const int pair = (int)((blockIdx.x * blockDim.x + threadIdx.x) >> 5);
    const int lane = threadIdx.x & 31;
    if (pair >= n_pairs) return;

    const long long base = 6ll * pair;  // element offset for the 2-query pack

    // --- indices first (gathers depend only on these) ---
    const int2 ia = __ldg((const int2*)(nidx + base + 0)); // i0_0, i1_0
    const int2 ib = __ldg((const int2*)(nidx + base + 2)); // i2_0, i0_1
    const int2 ic = __ldg((const int2*)(nidx + base + 4)); // i1_1, i2_1

    const int i00 = ia.x, i01 = ia.y, i02 = ib.x;
    const int i10 = ib.y, i11 = ic.x, i12 = ic.y;

    // --- launch all six feature-row gathers immediately (max MLP) ---
    const float4 a0 = __ldg((const float4*)(s_feats + (long long)i00 * C_FEAT) + lane);
    const float4 b0 = __ldg((const float4*)(s_feats + (long long)i01 * C_FEAT) + lane);
    const float4 c0 = __ldg((const float4*)(s_feats + (long long)i02 * C_FEAT) + lane);
    const float4 a1 = __ldg((const float4*)(s_feats + (long long)i10 * C_FEAT) + lane);
    const float4 b1 = __ldg((const float4*)(s_feats + (long long)i11 * C_FEAT) + lane);
    const float4 c1 = __ldg((const float4*)(s_feats + (long long)i12 * C_FEAT) + lane);

    // --- weight math overlaps the gather latency ---
    const float2 qa = __ldg((const float2*)(q_points + base + 0)); // q0.x q0.y
    const float2 qb = __ldg((const float2*)(q_points + base + 2)); // q0.z q1.x
    const float2 qc = __ldg((const float2*)(q_points + base + 4)); // q1.y q1.z

    float w00 = wgt(__ldg(&g_sp_pad[i00]), qa.x, qa.y, qb.x);
    float w01 = wgt(__ldg(&g_sp_pad[i01]), qa.x, qa.y, qb.x);
    float w02 = wgt(__ldg(&g_sp_pad[i02]), qa.x, qa.y, qb.x);
    float w10 = wgt(__ldg(&g_sp_pad[i10]), qb.y, qc.x, qc.y);
    float w11 = wgt(__ldg(&g_sp_pad[i11]), qb.y, qc.x, qc.y);
    float w12 = wgt(__ldg(&g_sp_pad[i12]), qb.y, qc.x, qc.y);

    float s0 = 1.0f / (w00 + w01 + w02);
    float s1 = 1.0f / (w10 + w11 + w12);
    w00 *= s0; w01 *= s0; w02 *= s0;
    w10 *= s1; w11 *= s1; w12 *= s1;

    float4 r0, r1;
    r0.x = w00 * a0.x + w01 * b0.x + w02 * c0.x;
    r0.y = w00 * a0.y + w01 * b0.y + w02 * c0.y;
    r0.z = w00 * a0.z + w01 * b0.z + w02 * c0.z;
    r0.w = w00 * a0.w + w01 * b0.w + w02 * c0.w;
    r1.x = w10 * a1.x + w11 * b1.x + w12 * c1.x;
    r1.y = w10 * a1.y + w11 * b1.y + w12 * c1.y;
    r1.z = w10 * a1.z + w11 * b1.z + w12 * c1.z;
    r1.w = w10 * a1.w + w11 * b1.w + w12 * c1.w;

    const long long m0 = 2ll * pair;
    out[m0 * (C_FEAT / 4) + lane] = r0;
    out[(m0 + 1) * (C_FEAT / 4) + lane] = r1;
}

extern "C" void kernel_launch(void* const* d_in, const int* in_sizes, int n_in,
                              void* d_out, int out_size)
{
    const float* s_feats = (const float*)d_in[0];
    const float* q_points = (const float*)d_in[1];
    const float* s_points = (const float*)d_in[2];
    const int* nidx = (const int*)d_in[3];
    float4* out = (float4*)d_out;

    const int M = in_sizes[1] / 3;   // 262144
    const int n_pairs = M / 2;       // M is even

    pack_points_kernel<<<(N_SRC + 255) / 256, 256>>>(s_points);

    const int warps_per_block = 8;   // 256 threads
    const int blocks = (n_pairs + warps_per_block - 1) / warps_per_block;
    knn_interp_kernel<<<blocks, warps_per_block * 32>>>(
        s_feats, q_points, nidx, out, n_pairs);
}

// round 4
// speedup vs baseline: 1.3201x; 1.3201x over previous
#include <cuda_runtime.h>

// KNNInterpolate, 3-pass latency-split:
//   pack:    s_points [N,3] -> padded float4 table (1 LDG.128 per neighbor pt)
//   weights: per query, compute normalized IDW weights; write packed idx/w
//   gather:  per query (1 warp), 2 broadcast meta loads + 3 row gathers + store
//
// Inputs (metadata order):
//   d_in[0] s_feats          float32 [65536, 128]
//   d_in[1] q_points         float32 [262144, 3]
//   d_in[2] s_points         float32 [65536, 3]
//   d_in[3] neighbor_indices int32   [262144, 3]
// Output: float32 [262144, 128]

#define C_FEAT 128
#define N_SRC 65536
#define M_QRY 262144
#define EPS 1e-8f

__device__ float4 g_sp_pad[N_SRC];   // padded xyz
__device__ int4   g_idx4[M_QRY];     // i0,i1,i2,pad
__device__ float4 g_w4[M_QRY];       // w0,w1,w2,pad

__global__ __launch_bounds__(256) void pack_points_kernel(
    const float* __restrict__ s_points)
{
    int i = blockIdx.x * blockDim.x + threadIdx.x;
    if (i < N_SRC) {
        float x = __ldg(s_points + 3 * i + 0);
        float y = __ldg(s_points + 3 * i + 1);
        float z = __ldg(s_points + 3 * i + 2);
        g_sp_pad[i] = make_float4(x, y, z, 0.0f);
    }
}

__device__ __forceinline__ float wgt(float4 p, float qx, float qy, float qz)
{
    float dx = qx - p.x, dy = qy - p.y, dz = qz - p.z;
    return 1.0f / (dx * dx + dy * dy + dz * dz + EPS);
}

// One thread per query: compute weights, store packed metadata.
__global__ __launch_bounds__(256) void weights_kernel(
    const float* __restrict__ q_points,
    const int* __restrict__ nidx,
    int M)
{
    int m = blockIdx.x * blockDim.x + threadIdx.x;
    if (m >= M) return;

    const int i0 = __ldg(nidx + 3ll * m + 0);
    const int i1 = __ldg(nidx + 3ll * m + 1);
    const int i2 = __ldg(nidx + 3ll * m + 2);

    const float qx = __ldg(q_points + 3ll * m + 0);
    const float qy = __ldg(q_points + 3ll * m + 1);
    const float qz = __ldg(q_points + 3ll * m + 2);

    float w0 = wgt(__ldg(&g_sp_pad[i0]), qx, qy, qz);
    float w1 = wgt(__ldg(&g_sp_pad[i1]), qx, qy, qz);
    float w2 = wgt(__ldg(&g_sp_pad[i2]), qx, qy, qz);
    const float s = 1.0f / (w0 + w1 + w2);

    g_idx4[m] = make_int4(i0, i1, i2, 0);
    g_w4[m] = make_float4(w0 * s, w1 * s, w2 * s, 0.0f);
}

// One warp per query: minimal chain, minimal registers, full occupancy.
__global__ __launch_bounds__(256) void gather_kernel(
    const float* __restrict__ s_feats,
    float4* __restrict__ out,
    int M)
{
    const int m = (int)((blockIdx.x * blockDim.x + threadIdx.x) >> 5);
    const int lane = threadIdx.x & 31;
    if (m >= M) return;

    const int4 iv = __ldg(&g_idx4[m]);     // broadcast
    const float4 wv = __ldg(&g_w4[m]);     // broadcast

    const float4 a = __ldg((const float4*)(s_feats + (long long)iv.x * C_FEAT) + lane);
    const float4 b = __ldg((const float4*)(s_feats + (long long)iv.y * C_FEAT) + lane);
    const float4 c = __ldg((const float4*)(s_feats + (long long)iv.z * C_FEAT) + lane);

    float4 r;
    r.x = wv.x * a.x;
    r.y = wv.x * a.y;
    r.z = wv.x * a.z;
    r.w = wv.x * a.w;
    r.x = fmaf(wv.y, b.x, r.x);
    r.y = fmaf(wv.y, b.y, r.y);
    r.z = fmaf(wv.y, b.z, r.z);
    r.w = fmaf(wv.y, b.w, r.w);
    r.x = fmaf(wv.z, c.x, r.x);
    r.y = fmaf(wv.z, c.y, r.y);
    r.z = fmaf(wv.z, c.z, r.z);
    r.w = fmaf(wv.z, c.w, r.w);

    out[(long long)m * (C_FEAT / 4) + lane] = r;
}

extern "C" void kernel_launch(void* const* d_in, const int* in_sizes, int n_in,
                              void* d_out, int out_size)
{
    const float* s_feats = (const float*)d_in[0];
    const float* q_points = (const float*)d_in[1];
    const float* s_points = (const float*)d_in[2];
    const int* nidx = (const int*)d_in[3];
    float4* out = (float4*)d_out;

    const int M = in_sizes[1] / 3;   // 262144

    pack_points_kernel<<<(N_SRC + 255) / 256, 256>>>(s_points);
    weights_kernel<<<(M + 255) / 256, 256>>>(q_points, nidx, M);

    const int warps_per_block = 8;   // 256 threads
    const int blocks = (M + warps_per_block - 1) / warps_per_block;
    gather_kernel<<<blocks, warps_per_block * 32>>>(s_feats, out, M);
}

// round 5
// speedup vs baseline: 1.4437x; 1.0936x over previous
#include <cuda_runtime.h>

// KNNInterpolate, 2-pass latency-split:
//   weights: per query (1 thread), compute normalized IDW weights from raw
//            s_points; write packed idx4 / w4 metadata.
//   gather:  per warp, TWO queries: 4 broadcast meta loads -> 6 independent
//            row gathers in flight -> FMA -> 2 streaming stores.
//
// Inputs (metadata order):
//   d_in[0] s_feats          float32 [65536, 128]
//   d_in[1] q_points         float32 [262144, 3]
//   d_in[2] s_points         float32 [65536, 3]
//   d_in[3] neighbor_indices int32   [262144, 3]
// Output: float32 [262144, 128]

#define C_FEAT 128
#define N_SRC 65536
#define M_QRY 262144
#define EPS 1e-8f

__device__ int4   g_idx4[M_QRY];     // i0,i1,i2,pad
__device__ float4 g_w4[M_QRY];       // w0,w1,w2,pad

__device__ __forceinline__ float wgt3(const float* __restrict__ sp, int i,
                                      float qx, float qy, float qz)
{
    float dx = qx - __ldg(sp + 3ll * i + 0);
    float dy = qy - __ldg(sp + 3ll * i + 1);
    float dz = qz - __ldg(sp + 3ll * i + 2);
    return 1.0f / (dx * dx + dy * dy + dz * dz + EPS);
}

// One thread per query: compute weights, store packed metadata.
__global__ __launch_bounds__(256) void weights_kernel(
    const float* __restrict__ q_points,
    const float* __restrict__ s_points,
    const int* __restrict__ nidx,
    int M)
{
    int m = blockIdx.x * blockDim.x + threadIdx.x;
    if (m >= M) return;

    const int i0 = __ldg(nidx + 3ll * m + 0);
    const int i1 = __ldg(nidx + 3ll * m + 1);
    const int i2 = __ldg(nidx + 3ll * m + 2);

    const float qx = __ldg(q_points + 3ll * m + 0);
    const float qy = __ldg(q_points + 3ll * m + 1);
    const float qz = __ldg(q_points + 3ll * m + 2);

    float w0 = wgt3(s_points, i0, qx, qy, qz);
    float w1 = wgt3(s_points, i1, qx, qy, qz);
    float w2 = wgt3(s_points, i2, qx, qy, qz);
    const float s = 1.0f / (w0 + w1 + w2);

    g_idx4[m] = make_int4(i0, i1, i2, 0);
    g_w4[m] = make_float4(w0 * s, w1 * s, w2 * s, 0.0f);
}

// One warp per TWO queries: doubled MLP, minimal chain, streaming stores.
__global__ __launch_bounds__(256, 6) void gather_kernel(
    const float* __restrict__ s_feats,
    float4* __restrict__ out,
    int n_pairs)
{
    const int pair = (int)((blockIdx.x * blockDim.x + threadIdx.x) >> 5);
    const int lane = threadIdx.x & 31;
    if (pair >= n_pairs) return;

    const int m0 = 2 * pair;

    // broadcast meta loads (independent; front-loaded by compiler)
    const int4 iv0 = __ldg(&g_idx4[m0]);
    const int4 iv1 = __ldg(&g_idx4[m0 + 1]);
    const float4 wv0 = __ldg(&g_w4[m0]);
    const float4 wv1 = __ldg(&g_w4[m0 + 1]);

    // six independent row gathers in flight
    const float4 a0 = __ldg((const float4*)(s_feats + (long long)iv0.x * C_FEAT) + lane);
    const float4 b0 = __ldg((const float4*)(s_feats + (long long)iv0.y * C_FEAT) + lane);
    const float4 c0 = __ldg((const float4*)(s_feats + (long long)iv0.z * C_FEAT) + lane);
    const float4 a1 = __ldg((const float4*)(s_feats + (long long)iv1.x * C_FEAT) + lane);
    const float4 b1 = __ldg((const float4*)(s_feats + (long long)iv1.y * C_FEAT) + lane);
    const float4 c1 = __ldg((const float4*)(s_feats + (long long)iv1.z * C_FEAT) + lane);

    float4 r0;
    r0.x = wv0.x * a0.x; r0.y = wv0.x * a0.y; r0.z = wv0.x * a0.z; r0.w = wv0.x * a0.w;
    r0.x = fmaf(wv0.y, b0.x, r0.x); r0.y = fmaf(wv0.y, b0.y, r0.y);
    r0.z = fmaf(wv0.y, b0.z, r0.z); r0.w = fmaf(wv0.y, b0.w, r0.w);
    r0.x = fmaf(wv0.z, c0.x, r0.x); r0.y = fmaf(wv0.z, c0.y, r0.y);
    r0.z = fmaf(wv0.z, c0.z, r0.z); r0.w = fmaf(wv0.z, c0.w, r0.w);

    float4 r1;
    r1.x = wv1.x * a1.x; r1.y = wv1.x * a1.y; r1.z = wv1.x * a1.z; r1.w = wv1.x * a1.w;
    r1.x = fmaf(wv1.y, b1.x, r1.x); r1.y = fmaf(wv1.y, b1.y, r1.y);
    r1.z = fmaf(wv1.y, b1.z, r1.z); r1.w = fmaf(wv1.y, b1.w, r1.w);
    r1.x = fmaf(wv1.z, c1.x, r1.x); r1.y = fmaf(wv1.z, c1.y, r1.y);
    r1.z = fmaf(wv1.z, c1.z, r1.z); r1.w = fmaf(wv1.z, c1.w, r1.w);

    // streaming stores: keep s_feats resident in L2
    float4* o0 = out + (long long)m0 * (C_FEAT / 4) + lane;
    __stcs(o0, r0);
    __stcs(o0 + (C_FEAT / 4), r1);
}

extern "C" void kernel_launch(void* const* d_in, const int* in_sizes, int n_in,
                              void* d_out, int out_size)
{
    const float* s_feats = (const float*)d_in[0];
    const float* q_points = (const float*)d_in[1];
    const float* s_points = (const float*)d_in[2];
    const int* nidx = (const int*)d_in[3];
    float4* out = (float4*)d_out;

    const int M = in_sizes[1] / 3;   // 262144
    const int n_pairs = M / 2;

    weights_kernel<<<(M + 255) / 256, 256>>>(q_points, s_points, nidx, M);

    const int warps_per_block = 8;   // 256 threads
    const int blocks = (n_pairs + warps_per_block - 1) / warps_per_block;
    gather_kernel<<<blocks, warps_per_block * 32>>>(s_feats, out, n_pairs);
}